// round 6
// baseline (speedup 1.0000x reference)
#include <cuda_runtime.h>
#include <mma.h>
#include <math.h>

using namespace nvcuda;

#define NATOMS  10000
#define NEDGES  160000
#define FEAT    128
#define F3      384
#define NRBF    20
#define PI_F    3.14159265358979f
#define CUT_F   5.0f

// ---------------- scratch (device globals; no allocation allowed) ----------
__device__ float g_s     [NATOMS * FEAT];
__device__ float g_vA    [NATOMS * F3];
__device__ float g_vB    [NATOMS * F3];
__device__ float g_phi   [NATOMS * F3];
__device__ float g_h     [NATOMS * FEAT];
__device__ float g_stack [NATOMS * 2 * FEAT];
__device__ float g_uv    [NATOMS * F3];
__device__ float g_vv    [NATOMS * F3];
__device__ float g_sp    [NATOMS * F3];
__device__ float g_t     [NATOMS * 64];
__device__ float g_rbf   [NEDGES * NRBF];
__device__ float g_env   [NEDGES];
__device__ float g_unit  [NEDGES * 3];
// CSR over destination atom i
__device__ int   g_deg   [NATOMS];
__device__ int   g_cur   [NATOMS];
__device__ int   g_off   [NATOMS + 1];
__device__ int   g_eid   [NEDGES];

__device__ __forceinline__ float silu_f(float x) { return x / (1.0f + expf(-x)); }

// ---------------- edge geometry precompute (layer-invariant) ---------------
__global__ void edge_pre_kernel(const float* __restrict__ xyz,
                                const int2* __restrict__ nbr, int E)
{
    int e = blockIdx.x * blockDim.x + threadIdx.x;
    if (e >= E) return;
    int2 ij = nbr[e];
    float rx = xyz[ij.y * 3 + 0] - xyz[ij.x * 3 + 0];
    float ry = xyz[ij.y * 3 + 1] - xyz[ij.x * 3 + 1];
    float rz = xyz[ij.y * 3 + 2] - xyz[ij.x * 3 + 2];
    float d2 = rx * rx + ry * ry + rz * rz + 3.0f * 1e-15f;
    float dist = sqrtf(d2);
    float inv = 1.0f / dist;
    g_unit[e * 3 + 0] = rx * inv;
    g_unit[e * 3 + 1] = ry * inv;
    g_unit[e * 3 + 2] = rz * inv;
    g_env[e] = (dist < CUT_F) ? 0.5f * (cosf(PI_F * dist / CUT_F) + 1.0f) : 0.0f;
#pragma unroll
    for (int k = 0; k < NRBF; k++) {
        float kn = (float)(k + 1) * (PI_F / CUT_F);
        g_rbf[e * NRBF + k] = sinf(kn * dist) * inv;
    }
}

// ---------------- CSR construction -----------------------------------------
__global__ void hist_kernel(const int2* __restrict__ nbr, int E)
{
    int e = blockIdx.x * blockDim.x + threadIdx.x;
    if (e >= E) return;
    atomicAdd(&g_deg[nbr[e].x], 1);
}

__global__ void scan_kernel(int N)
{
    __shared__ int sm[1024];
    int tid = threadIdx.x;
    int chunk = (N + 1023) >> 10;
    int lo = tid * chunk;
    int hi = lo + chunk; if (hi > N) hi = N;
    int s = 0;
    for (int a = lo; a < hi; a++) s += g_deg[a];
    sm[tid] = s;
    __syncthreads();
    for (int off = 1; off < 1024; off <<= 1) {
        int v = (tid >= off) ? sm[tid - off] : 0;
        __syncthreads();
        sm[tid] += v;
        __syncthreads();
    }
    int base = (tid == 0) ? 0 : sm[tid - 1];
    for (int a = lo; a < hi; a++) {
        g_off[a] = base;
        base += g_deg[a];
    }
    if (tid == 1023) g_off[N] = base;
}

__global__ void scatter_kernel(const int2* __restrict__ nbr, int E)
{
    int e = blockIdx.x * blockDim.x + threadIdx.x;
    if (e >= E) return;
    int i = nbr[e].x;
    int p = atomicAdd(&g_cur[i], 1);
    g_eid[g_off[i] + p] = e;
}

// deterministic: sort each atom's edge list ascending (insertion sort, deg~16)
__global__ void sortcsr_kernel(int N)
{
    int a = blockIdx.x * blockDim.x + threadIdx.x;
    if (a >= N) return;
    int lo = g_off[a], hi = g_off[a + 1];
    for (int x = lo + 1; x < hi; x++) {
        int key = g_eid[x];
        int y = x - 1;
        while (y >= lo && g_eid[y] > key) { g_eid[y + 1] = g_eid[y]; y--; }
        g_eid[y + 1] = key;
    }
}

// ---------------- s init: s = embed[z] -------------------------------------
__global__ void init_s_kernel(const float* __restrict__ embed,
                              const int* __restrict__ z, int N)
{
    int idx = blockIdx.x * blockDim.x + threadIdx.x;
    if (idx >= N * FEAT) return;
    int n = idx >> 7, f = idx & 127;
    g_s[idx] = embed[z[n] * FEAT + f];
}

// ---------------- 3xTF32 WMMA GEMM: C = act(A[MxK] @ B[KxN] + bias) --------
// Split each operand x = hi + lo (hi = tf32(x), lo = tf32(x - hi)).
// acc += hi_a*hi_b + hi_a*lo_b + lo_a*hi_b  (lo*lo dropped, ~2^-22 rel).
// Block tile 128x64, BK=32, 8 warps (256 thr). Warp tile 32x32 (2x2 wmma 16x16x8).
#define BM 128
#define BN 64
#define BK 32
#define LDA (BK + 8)     // 40
#define LDB (BN + 8)     // 72
#define LDC (BN + 8)     // 72
#define SMEM_FLOATS 9216

__global__ __launch_bounds__(256) void gemm_tf32_kernel(
    const float* __restrict__ A, const float* __restrict__ B,
    const float* __restrict__ bias, float* __restrict__ C,
    int M, int N, int K, int act)
{
    __shared__ float smem[SMEM_FLOATS];
    float* As = smem;                       // [BM][LDA]
    float* Bs = smem + BM * LDA;            // [BK][LDB]
    float* Cs = smem;                       // [BM][LDC] (reused)

    int tid  = threadIdx.x;
    int warp = tid >> 5;
    int wm   = warp & 3;        // warp row 0..3 -> 32*wm
    int wn   = warp >> 2;       // warp col 0..1 -> 32*wn
    int brow = blockIdx.y * BM;
    int bcol = blockIdx.x * BN;

    wmma::fragment<wmma::accumulator, 16, 16, 8, float> acc[2][2];
#pragma unroll
    for (int i = 0; i < 2; i++)
#pragma unroll
        for (int j = 0; j < 2; j++)
            wmma::fill_fragment(acc[i][j], 0.0f);

    for (int k0 = 0; k0 < K; k0 += BK) {
        // load A tile 128x32
        {
            int ar = tid >> 1;
            int ac = (tid & 1) * 16;
            bool okr = (brow + ar) < M;
            const float* Ag = A + (size_t)(brow + ar) * K + k0 + ac;
            float* dst = &As[ar * LDA + ac];
#pragma unroll
            for (int q = 0; q < 4; q++) {
                float4 v = okr ? *(const float4*)(Ag + q * 4)
                               : make_float4(0.f, 0.f, 0.f, 0.f);
                *(float4*)(dst + q * 4) = v;
            }
        }
        // load B tile 32x64
        {
            int br = tid >> 3;
            int bc = (tid & 7) * 8;
            const float* Bg = B + (size_t)(k0 + br) * N + bcol + bc;
            float* dst = &Bs[br * LDB + bc];
            *(float4*)(dst)     = *(const float4*)(Bg);
            *(float4*)(dst + 4) = *(const float4*)(Bg + 4);
        }
        __syncthreads();

#pragma unroll
        for (int ks = 0; ks < BK; ks += 8) {
            wmma::fragment<wmma::matrix_a, 16, 16, 8,
                           wmma::precision::tf32, wmma::row_major> a_hi[2], a_lo[2];
            wmma::fragment<wmma::matrix_b, 16, 16, 8,
                           wmma::precision::tf32, wmma::row_major> b_hi[2], b_lo[2];
#pragma unroll
            for (int i = 0; i < 2; i++) {
                wmma::load_matrix_sync(a_hi[i], &As[(wm * 32 + i * 16) * LDA + ks], LDA);
#pragma unroll
                for (int t = 0; t < a_hi[i].num_elements; t++) {
                    float x  = a_hi[i].x[t];
                    float hi = wmma::__float_to_tf32(x);
                    a_hi[i].x[t] = hi;
                    a_lo[i].x[t] = wmma::__float_to_tf32(x - hi);
                }
            }
#pragma unroll
            for (int j = 0; j < 2; j++) {
                wmma::load_matrix_sync(b_hi[j], &Bs[ks * LDB + wn * 32 + j * 16], LDB);
#pragma unroll
                for (int t = 0; t < b_hi[j].num_elements; t++) {
                    float x  = b_hi[j].x[t];
                    float hi = wmma::__float_to_tf32(x);
                    b_hi[j].x[t] = hi;
                    b_lo[j].x[t] = wmma::__float_to_tf32(x - hi);
                }
            }
#pragma unroll
            for (int i = 0; i < 2; i++)
#pragma unroll
                for (int j = 0; j < 2; j++) {
                    wmma::mma_sync(acc[i][j], a_hi[i], b_lo[j], acc[i][j]);
                    wmma::mma_sync(acc[i][j], a_lo[i], b_hi[j], acc[i][j]);
                    wmma::mma_sync(acc[i][j], a_hi[i], b_hi[j], acc[i][j]);
                }
        }
        __syncthreads();
    }

    // epilogue: stage to shared, then bias+act+store
#pragma unroll
    for (int i = 0; i < 2; i++)
#pragma unroll
        for (int j = 0; j < 2; j++)
            wmma::store_matrix_sync(
                &Cs[(wm * 32 + i * 16) * LDC + wn * 32 + j * 16],
                acc[i][j], LDC, wmma::mem_row_major);
    __syncthreads();

    {
        int row = tid >> 1;                 // 0..127
        int cb  = (tid & 1) * 32;           // 0 or 32
        if (brow + row < M) {
            float* dst = &C[(size_t)(brow + row) * N + bcol + cb];
            const float* src = &Cs[row * LDC + cb];
#pragma unroll
            for (int q = 0; q < 8; q++) {
                float4 v = *(const float4*)(src + q * 4);
                float* pv = (float*)&v;
#pragma unroll
                for (int u = 0; u < 4; u++) {
                    float x = pv[u];
                    if (bias) x += bias[bcol + cb + q * 4 + u];
                    if (act) x = silu_f(x);
                    pv[u] = x;
                }
                *(float4*)(dst + q * 4) = v;
            }
        }
    }
}

// ---------------- edge message pass, CSR gather (no atomics) ---------------
__global__ __launch_bounds__(128) void msg_csr_kernel(
    const int2* __restrict__ nbr,
    const float* __restrict__ phi,
    const float* __restrict__ vin,
    float* __restrict__ vout,
    float* __restrict__ s,
    const float* __restrict__ dwl,
    const float* __restrict__ dbl, int N)
{
    int f = threadIdx.x;
    float w0[NRBF], w1[NRBF], w2[NRBF];
#pragma unroll
    for (int k = 0; k < NRBF; k++) {
        w0[k] = dwl[k * F3 + f];
        w1[k] = dwl[k * F3 + FEAT + f];
        w2[k] = dwl[k * F3 + 2 * FEAT + f];
    }
    float b0 = dbl[f], b1 = dbl[FEAT + f], b2 = dbl[2 * FEAT + f];

    for (int a = blockIdx.x; a < N; a += gridDim.x) {
        int lo = g_off[a], hi = g_off[a + 1];
        float accs = 0.f, av0 = 0.f, av1 = 0.f, av2 = 0.f;
        for (int t = lo; t < hi; t++) {
            int e = g_eid[t];
            int j = nbr[e].y;
            float env = g_env[e];
            float ux = g_unit[e * 3 + 0];
            float uy = g_unit[e * 3 + 1];
            float uz = g_unit[e * 3 + 2];
            const float4* r4 = (const float4*)&g_rbf[e * NRBF];
            float ws0 = b0, ws1 = b1, ws2 = b2;
#pragma unroll
            for (int q = 0; q < 5; q++) {
                float4 r = r4[q];
                ws0 += r.x * w0[q * 4 + 0] + r.y * w0[q * 4 + 1]
                     + r.z * w0[q * 4 + 2] + r.w * w0[q * 4 + 3];
                ws1 += r.x * w1[q * 4 + 0] + r.y * w1[q * 4 + 1]
                     + r.z * w1[q * 4 + 2] + r.w * w1[q * 4 + 3];
                ws2 += r.x * w2[q * 4 + 0] + r.y * w2[q * 4 + 1]
                     + r.z * w2[q * 4 + 2] + r.w * w2[q * 4 + 3];
            }
            ws0 *= env; ws1 *= env; ws2 *= env;
            const float* pj = &phi[(size_t)j * F3];
            const float* vj = &vin[(size_t)j * F3];
            float inv0 = pj[f]            * ws0;
            float inv1 = pj[FEAT + f]     * ws1;
            float inv2 = pj[2 * FEAT + f] * ws2;
            accs += inv1;
            av0 += inv0 * vj[f]            + inv2 * ux;
            av1 += inv0 * vj[FEAT + f]     + inv2 * uy;
            av2 += inv0 * vj[2 * FEAT + f] + inv2 * uz;
        }
        s[(size_t)a * FEAT + f] += accs;
        const float* va = &vin[(size_t)a * F3];
        float* vo = &vout[(size_t)a * F3];
        vo[f]            = va[f]            + av0;
        vo[FEAT + f]     = va[FEAT + f]     + av1;
        vo[2 * FEAT + f] = va[2 * FEAT + f] + av2;
    }
}

// ---------------- vv-norm + stack [s | ||v_v||] ----------------------------
__global__ void stack_kernel(int N)
{
    int idx = blockIdx.x * blockDim.x + threadIdx.x;
    if (idx >= N * FEAT) return;
    int n = idx >> 7, g = idx & 127;
    float a = g_vv[n * F3 + g];
    float b = g_vv[n * F3 + FEAT + g];
    float c = g_vv[n * F3 + 2 * FEAT + g];
    g_stack[n * 2 * FEAT + g] = g_s[idx];
    g_stack[n * 2 * FEAT + FEAT + g] = sqrtf(a * a + b * b + c * c + 1e-15f);
}

// ---------------- per-atom update ------------------------------------------
__global__ void update_kernel(float* __restrict__ v, int N)
{
    int idx = blockIdx.x * blockDim.x + threadIdx.x;
    if (idx >= N * FEAT) return;
    int n = idx >> 7, g = idx & 127;
    float sp0 = g_sp[n * F3 + g];
    float sp1 = g_sp[n * F3 + FEAT + g];
    float sp2 = g_sp[n * F3 + 2 * FEAT + g];
    float acc = 0.f;
#pragma unroll
    for (int d = 0; d < 3; d++) {
        float uv = g_uv[n * F3 + d * FEAT + g];
        v[n * F3 + d * FEAT + g] += uv * sp0;
        acc += uv * g_vv[n * F3 + d * FEAT + g];
    }
    g_s[idx] += acc * sp1 + sp2;
}

// ---------------- force readout: warp per edge, t = s@W1 precomputed -------
__global__ __launch_bounds__(256) void readout_kernel(
    const float* __restrict__ xyz,
    const int2* __restrict__ nbr,
    const float* __restrict__ b1,
    const float* __restrict__ w2,
    const float* __restrict__ b2v,
    float* __restrict__ out, int E)
{
    __shared__ float sb1[64], sw2[64];
    int tid = threadIdx.x;   // 256 = 8 warps
    if (tid < 64) { sb1[tid] = b1[tid]; sw2[tid] = w2[tid]; }
    __syncthreads();
    float b2 = b2v[0];
    int warp = tid >> 5, lane = tid & 31;
    int nwarps = gridDim.x * 8;
    for (int e = blockIdx.x * 8 + warp; e < E; e += nwarps) {
        int2 ij = nbr[e];
        const float* ti = &g_t[(size_t)ij.x * 64];
        const float* tj = &g_t[(size_t)ij.y * 64];
        float h0 = ti[lane]      + tj[lane]      + sb1[lane];
        float h1 = ti[lane + 32] + tj[lane + 32] + sb1[lane + 32];
        float p = silu_f(h0) * sw2[lane] + silu_f(h1) * sw2[lane + 32];
#pragma unroll
        for (int o = 16; o; o >>= 1) p += __shfl_xor_sync(0xffffffffu, p, o);
        float fs = p + b2;
        float dx = xyz[ij.x * 3 + 0] - xyz[ij.y * 3 + 0];
        float dy = xyz[ij.x * 3 + 1] - xyz[ij.y * 3 + 1];
        float dz = xyz[ij.x * 3 + 2] - xyz[ij.y * 3 + 2];
        float dis = sqrtf(dx * dx + dy * dy + dz * dz);
        if (lane < 3) {
            float dcomp = (lane == 0) ? dx : (lane == 1) ? dy : dz;
            float fe = fs * dcomp / dis;
            atomicAdd(&out[ij.x * 3 + lane], fe);
            atomicAdd(&out[ij.y * 3 + lane], -fe);
        }
    }
}

// ---------------- host orchestration ---------------------------------------
static void run_gemm(const float* A, const float* B, const float* bias, float* C,
                     int M, int N, int K, int act)
{
    dim3 grid(N / BN, (M + BM - 1) / BM);
    gemm_tf32_kernel<<<grid, 256>>>(A, B, bias, C, M, N, K, act);
}

extern "C" void kernel_launch(void* const* d_in, const int* in_sizes, int n_in,
                              void* d_out, int out_size)
{
    const float* xyz    = (const float*)d_in[0];
    const int*   z      = (const int*)  d_in[1];
    const int2*  nbr    = (const int2*) d_in[2];
    const float* embed  = (const float*)d_in[3];
    const float* msg_w1 = (const float*)d_in[4];
    const float* msg_b1 = (const float*)d_in[5];
    const float* msg_w2 = (const float*)d_in[6];
    const float* msg_b2 = (const float*)d_in[7];
    const float* dist_w = (const float*)d_in[8];
    const float* dist_b = (const float*)d_in[9];
    const float* upd_u  = (const float*)d_in[10];
    const float* upd_v  = (const float*)d_in[11];
    const float* upd_w1 = (const float*)d_in[12];
    const float* upd_b1 = (const float*)d_in[13];
    const float* upd_w2 = (const float*)d_in[14];
    const float* upd_b2 = (const float*)d_in[15];
    const float* ero_w1 = (const float*)d_in[16];
    const float* ero_b1 = (const float*)d_in[17];
    const float* ero_w2 = (const float*)d_in[18];
    const float* ero_b2 = (const float*)d_in[19];

    const int N = in_sizes[1];          // 10000
    const int E = in_sizes[2] / 2;      // 160000

    float *s_p, *vA_p, *vB_p, *phi_p, *h_p, *stk_p, *uv_p, *vv_p, *sp_p, *t_p;
    int *deg_p, *cur_p;
    cudaGetSymbolAddress((void**)&s_p,   g_s);
    cudaGetSymbolAddress((void**)&vA_p,  g_vA);
    cudaGetSymbolAddress((void**)&vB_p,  g_vB);
    cudaGetSymbolAddress((void**)&phi_p, g_phi);
    cudaGetSymbolAddress((void**)&h_p,   g_h);
    cudaGetSymbolAddress((void**)&stk_p, g_stack);
    cudaGetSymbolAddress((void**)&uv_p,  g_uv);
    cudaGetSymbolAddress((void**)&vv_p,  g_vv);
    cudaGetSymbolAddress((void**)&sp_p,  g_sp);
    cudaGetSymbolAddress((void**)&t_p,   g_t);
    cudaGetSymbolAddress((void**)&deg_p, g_deg);
    cudaGetSymbolAddress((void**)&cur_p, g_cur);

    const size_t VBYTES = (size_t)N * F3 * sizeof(float);

    // init + CSR build
    cudaMemsetAsync(vA_p, 0, VBYTES, 0);
    cudaMemsetAsync(deg_p, 0, N * sizeof(int), 0);
    cudaMemsetAsync(cur_p, 0, N * sizeof(int), 0);
    init_s_kernel<<<(N * FEAT + 255) / 256, 256>>>(embed, z, N);
    edge_pre_kernel<<<(E + 255) / 256, 256>>>(xyz, nbr, E);
    hist_kernel<<<(E + 255) / 256, 256>>>(nbr, E);
    scan_kernel<<<1, 1024>>>(N);
    scatter_kernel<<<(E + 255) / 256, 256>>>(nbr, E);
    sortcsr_kernel<<<(N + 127) / 128, 128>>>(N);

    float* vcur = vA_p;
    float* vnxt = vB_p;
    for (int l = 0; l < 3; l++) {
        // phi = silu(s @ W1 + b1) @ W2 + b2
        run_gemm(s_p, msg_w1 + (size_t)l * FEAT * FEAT, msg_b1 + l * FEAT,
                 h_p, N, FEAT, FEAT, 1);
        run_gemm(h_p, msg_w2 + (size_t)l * FEAT * F3, msg_b2 + l * F3,
                 phi_p, N, F3, FEAT, 0);
        // gather message pass: s in place, v out-of-place
        msg_csr_kernel<<<2048, 128>>>(nbr, phi_p, vcur, vnxt, s_p,
                                      dist_w + (size_t)l * NRBF * F3,
                                      dist_b + l * F3, N);
        // update stage
        run_gemm(vnxt, upd_u + (size_t)l * FEAT * FEAT, nullptr, uv_p,
                 N * 3, FEAT, FEAT, 0);
        run_gemm(vnxt, upd_v + (size_t)l * FEAT * FEAT, nullptr, vv_p,
                 N * 3, FEAT, FEAT, 0);
        stack_kernel<<<(N * FEAT + 255) / 256, 256>>>(N);
        run_gemm(stk_p, upd_w1 + (size_t)l * 2 * FEAT * FEAT, upd_b1 + l * FEAT,
                 h_p, N, FEAT, 2 * FEAT, 1);
        run_gemm(h_p, upd_w2 + (size_t)l * FEAT * F3, upd_b2 + l * F3,
                 sp_p, N, F3, FEAT, 0);
        update_kernel<<<(N * FEAT + 255) / 256, 256>>>(vnxt, N);
        float* t = vcur; vcur = vnxt; vnxt = t;
    }

    // readout: t = s @ ero_w1 (no bias), then light edge kernel
    run_gemm(s_p, ero_w1, nullptr, t_p, N, 64, FEAT, 0);
    cudaMemsetAsync(d_out, 0, (size_t)out_size * sizeof(float), 0);
    readout_kernel<<<2048, 256>>>(xyz, nbr, ero_b1, ero_w2, ero_b2,
                                  (float*)d_out, E);
}

// round 8
// speedup vs baseline: 1.2324x; 1.2324x over previous
#include <cuda_runtime.h>
#include <math.h>

#define NATOMS  10000
#define NEDGES  160000
#define FEAT    128
#define F3      384
#define NRBF    20
#define PI_F    3.14159265358979f
#define CUT_F   5.0f

// ---------------- scratch (device globals; no allocation allowed) ----------
__device__ float g_s     [NATOMS * FEAT];
__device__ float g_vA    [NATOMS * F3];
__device__ float g_vB    [NATOMS * F3];
__device__ float g_phi   [NATOMS * F3];
__device__ float g_h     [NATOMS * FEAT];
__device__ float g_stack [NATOMS * 2 * FEAT];
__device__ float g_uv    [NATOMS * F3];
__device__ float g_vv    [NATOMS * F3];
__device__ float g_sp    [NATOMS * F3];
__device__ float g_t     [NATOMS * 64];
__device__ float g_rbf   [NEDGES * NRBF];
__device__ float g_env   [NEDGES];
__device__ float g_unit  [NEDGES * 3];
// CSR over destination atom i
__device__ int   g_deg   [NATOMS];
__device__ int   g_cur   [NATOMS];
__device__ int   g_off   [NATOMS + 1];
__device__ int   g_eid   [NEDGES];

__device__ __forceinline__ float silu_f(float x) { return x / (1.0f + expf(-x)); }

// ---------------- edge geometry precompute (layer-invariant) ---------------
__global__ void edge_pre_kernel(const float* __restrict__ xyz,
                                const int2* __restrict__ nbr, int E)
{
    int e = blockIdx.x * blockDim.x + threadIdx.x;
    if (e >= E) return;
    int2 ij = nbr[e];
    float rx = xyz[ij.y * 3 + 0] - xyz[ij.x * 3 + 0];
    float ry = xyz[ij.y * 3 + 1] - xyz[ij.x * 3 + 1];
    float rz = xyz[ij.y * 3 + 2] - xyz[ij.x * 3 + 2];
    float d2 = rx * rx + ry * ry + rz * rz + 3.0f * 1e-15f;
    float dist = sqrtf(d2);
    float inv = 1.0f / dist;
    g_unit[e * 3 + 0] = rx * inv;
    g_unit[e * 3 + 1] = ry * inv;
    g_unit[e * 3 + 2] = rz * inv;
    g_env[e] = (dist < CUT_F) ? 0.5f * (cosf(PI_F * dist / CUT_F) + 1.0f) : 0.0f;
#pragma unroll
    for (int k = 0; k < NRBF; k++) {
        float kn = (float)(k + 1) * (PI_F / CUT_F);
        g_rbf[e * NRBF + k] = sinf(kn * dist) * inv;
    }
}

// ---------------- CSR construction -----------------------------------------
__global__ void hist_kernel(const int2* __restrict__ nbr, int E)
{
    int e = blockIdx.x * blockDim.x + threadIdx.x;
    if (e >= E) return;
    atomicAdd(&g_deg[nbr[e].x], 1);
}

__global__ void scan_kernel(int N)
{
    __shared__ int sm[1024];
    int tid = threadIdx.x;
    int chunk = (N + 1023) >> 10;
    int lo = tid * chunk;
    int hi = lo + chunk; if (hi > N) hi = N;
    int s = 0;
    for (int a = lo; a < hi; a++) s += g_deg[a];
    sm[tid] = s;
    __syncthreads();
    for (int off = 1; off < 1024; off <<= 1) {
        int v = (tid >= off) ? sm[tid - off] : 0;
        __syncthreads();
        sm[tid] += v;
        __syncthreads();
    }
    int base = (tid == 0) ? 0 : sm[tid - 1];
    for (int a = lo; a < hi; a++) {
        g_off[a] = base;
        base += g_deg[a];
    }
    if (tid == 1023) g_off[N] = base;
}

__global__ void scatter_kernel(const int2* __restrict__ nbr, int E)
{
    int e = blockIdx.x * blockDim.x + threadIdx.x;
    if (e >= E) return;
    int i = nbr[e].x;
    int p = atomicAdd(&g_cur[i], 1);
    g_eid[g_off[i] + p] = e;
}

// deterministic: sort each atom's edge list ascending (insertion sort, deg~16)
__global__ void sortcsr_kernel(int N)
{
    int a = blockIdx.x * blockDim.x + threadIdx.x;
    if (a >= N) return;
    int lo = g_off[a], hi = g_off[a + 1];
    for (int x = lo + 1; x < hi; x++) {
        int key = g_eid[x];
        int y = x - 1;
        while (y >= lo && g_eid[y] > key) { g_eid[y + 1] = g_eid[y]; y--; }
        g_eid[y + 1] = key;
    }
}

// ---------------- s init: s = embed[z] -------------------------------------
__global__ void init_s_kernel(const float* __restrict__ embed,
                              const int* __restrict__ z, int N)
{
    int idx = blockIdx.x * blockDim.x + threadIdx.x;
    if (idx >= N * FEAT) return;
    int n = idx >> 7, f = idx & 127;
    g_s[idx] = embed[z[n] * FEAT + f];
}

// ---------------- tiled GEMM: C = act(A[MxK] @ B[KxN] + bias) --------------
// 128x64 tile, 256 threads, 8x4 micro-tile.  (R4-proven FFMA kernel)
#define TBM 128
#define TBN 64
#define TBK 16
#define APAD 132
__global__ __launch_bounds__(256) void gemm_kernel(
    const float* __restrict__ A, const float* __restrict__ B,
    const float* __restrict__ bias, float* __restrict__ C,
    int M, int N, int K, int act)
{
    __shared__ float As[TBK][APAD];   // [k][m], padded
    __shared__ float Bs[TBK][TBN];    // [k][n]
    int brow = blockIdx.y * TBM;
    int bcol = blockIdx.x * TBN;
    int tid = threadIdx.x;            // 256
    int tx = tid & 15;                // 16 col-groups of 4
    int ty = tid >> 4;                // 16 row-groups of 8
    float acc[8][4] = {};

    for (int k0 = 0; k0 < K; k0 += TBK) {
        {   // load A tile: 128 rows x 16 k. Each thread: 2 float4.
            int r = tid >> 2;                 // 0..63
            int c = (tid & 3) * 4;            // 0,4,8,12
#pragma unroll
            for (int it = 0; it < 2; it++) {
                int row = brow + r + it * 64;
                float4 av = make_float4(0.f, 0.f, 0.f, 0.f);
                if (row < M) av = *(const float4*)&A[(size_t)row * K + k0 + c];
                As[c + 0][r + it * 64] = av.x;
                As[c + 1][r + it * 64] = av.y;
                As[c + 2][r + it * 64] = av.z;
                As[c + 3][r + it * 64] = av.w;
            }
        }
        {   // load B tile: 16 rows x 64 cols. Each thread: 1 float4.
            int r = tid >> 4;                 // 0..15
            int c = (tid & 15) * 4;           // 0..60
            *(float4*)&Bs[r][c] = *(const float4*)&B[(size_t)(k0 + r) * N + bcol + c];
        }
        __syncthreads();
#pragma unroll
        for (int k = 0; k < TBK; k++) {
            float4 a0 = *(float4*)&As[k][ty * 8 + 0];
            float4 a1 = *(float4*)&As[k][ty * 8 + 4];
            float4 b  = *(float4*)&Bs[k][tx * 4];
            float ar[8] = {a0.x, a0.y, a0.z, a0.w, a1.x, a1.y, a1.z, a1.w};
#pragma unroll
            for (int i = 0; i < 8; i++) {
                acc[i][0] += ar[i] * b.x;
                acc[i][1] += ar[i] * b.y;
                acc[i][2] += ar[i] * b.z;
                acc[i][3] += ar[i] * b.w;
            }
        }
        __syncthreads();
    }
    float bv[4] = {0.f, 0.f, 0.f, 0.f};
    if (bias) {
#pragma unroll
        for (int j = 0; j < 4; j++) bv[j] = bias[bcol + tx * 4 + j];
    }
#pragma unroll
    for (int i = 0; i < 8; i++) {
        int grow = brow + ty * 8 + i;
        if (grow >= M) continue;
        float4 o;
        float* po = (float*)&o;
#pragma unroll
        for (int j = 0; j < 4; j++) {
            float v = acc[i][j] + bv[j];
            if (act) v = silu_f(v);
            po[j] = v;
        }
        *(float4*)&C[(size_t)grow * N + bcol + tx * 4] = o;
    }
}

// ---------------- dual GEMM: C1 = A@B1, C2 = A@B2 (K=N=128, no bias/act) ---
// Same A-tile serves two 64-wide outputs -> 2x FMA per shared-load.
__global__ __launch_bounds__(256) void gemm_dual_kernel(
    const float* __restrict__ A,
    const float* __restrict__ B1, float* __restrict__ C1,
    const float* __restrict__ B2, float* __restrict__ C2,
    int M)
{
    const int K = FEAT, N = FEAT;     // 128, 128
    __shared__ float As[TBK][APAD];
    __shared__ float Bs1[TBK][TBN];
    __shared__ float Bs2[TBK][TBN];
    int brow = blockIdx.y * TBM;
    int bcol = blockIdx.x * TBN;      // 0 or 64
    int tid = threadIdx.x;
    int tx = tid & 15;
    int ty = tid >> 4;
    float acc1[8][4] = {};
    float acc2[8][4] = {};

    for (int k0 = 0; k0 < K; k0 += TBK) {
        {
            int r = tid >> 2;
            int c = (tid & 3) * 4;
#pragma unroll
            for (int it = 0; it < 2; it++) {
                int row = brow + r + it * 64;
                float4 av = make_float4(0.f, 0.f, 0.f, 0.f);
                if (row < M) av = *(const float4*)&A[(size_t)row * K + k0 + c];
                As[c + 0][r + it * 64] = av.x;
                As[c + 1][r + it * 64] = av.y;
                As[c + 2][r + it * 64] = av.z;
                As[c + 3][r + it * 64] = av.w;
            }
        }
        {
            int r = tid >> 4;
            int c = (tid & 15) * 4;
            *(float4*)&Bs1[r][c] = *(const float4*)&B1[(size_t)(k0 + r) * N + bcol + c];
            *(float4*)&Bs2[r][c] = *(const float4*)&B2[(size_t)(k0 + r) * N + bcol + c];
        }
        __syncthreads();
#pragma unroll
        for (int k = 0; k < TBK; k++) {
            float4 a0 = *(float4*)&As[k][ty * 8 + 0];
            float4 a1 = *(float4*)&As[k][ty * 8 + 4];
            float4 b1 = *(float4*)&Bs1[k][tx * 4];
            float4 b2 = *(float4*)&Bs2[k][tx * 4];
            float ar[8] = {a0.x, a0.y, a0.z, a0.w, a1.x, a1.y, a1.z, a1.w};
#pragma unroll
            for (int i = 0; i < 8; i++) {
                acc1[i][0] += ar[i] * b1.x;
                acc1[i][1] += ar[i] * b1.y;
                acc1[i][2] += ar[i] * b1.z;
                acc1[i][3] += ar[i] * b1.w;
                acc2[i][0] += ar[i] * b2.x;
                acc2[i][1] += ar[i] * b2.y;
                acc2[i][2] += ar[i] * b2.z;
                acc2[i][3] += ar[i] * b2.w;
            }
        }
        __syncthreads();
    }
#pragma unroll
    for (int i = 0; i < 8; i++) {
        int grow = brow + ty * 8 + i;
        if (grow >= M) continue;
        float4 o1, o2;
        float *p1 = (float*)&o1, *p2 = (float*)&o2;
#pragma unroll
        for (int j = 0; j < 4; j++) { p1[j] = acc1[i][j]; p2[j] = acc2[i][j]; }
        *(float4*)&C1[(size_t)grow * N + bcol + tx * 4] = o1;
        *(float4*)&C2[(size_t)grow * N + bcol + tx * 4] = o2;
    }
}

// ---------------- edge message pass, CSR gather (no atomics) ---------------
__global__ __launch_bounds__(128) void msg_csr_kernel(
    const int2* __restrict__ nbr,
    const float* __restrict__ phi,
    const float* __restrict__ vin,
    float* __restrict__ vout,
    float* __restrict__ s,
    const float* __restrict__ dwl,
    const float* __restrict__ dbl, int N)
{
    int f = threadIdx.x;
    float w0[NRBF], w1[NRBF], w2[NRBF];
#pragma unroll
    for (int k = 0; k < NRBF; k++) {
        w0[k] = dwl[k * F3 + f];
        w1[k] = dwl[k * F3 + FEAT + f];
        w2[k] = dwl[k * F3 + 2 * FEAT + f];
    }
    float b0 = dbl[f], b1 = dbl[FEAT + f], b2 = dbl[2 * FEAT + f];

    for (int a = blockIdx.x; a < N; a += gridDim.x) {
        int lo = g_off[a], hi = g_off[a + 1];
        float accs = 0.f, av0 = 0.f, av1 = 0.f, av2 = 0.f;
        for (int t = lo; t < hi; t++) {
            int e = g_eid[t];
            int j = nbr[e].y;
            float env = g_env[e];
            float ux = g_unit[e * 3 + 0];
            float uy = g_unit[e * 3 + 1];
            float uz = g_unit[e * 3 + 2];
            const float4* r4 = (const float4*)&g_rbf[e * NRBF];
            float ws0 = b0, ws1 = b1, ws2 = b2;
#pragma unroll
            for (int q = 0; q < 5; q++) {
                float4 r = r4[q];
                ws0 += r.x * w0[q * 4 + 0] + r.y * w0[q * 4 + 1]
                     + r.z * w0[q * 4 + 2] + r.w * w0[q * 4 + 3];
                ws1 += r.x * w1[q * 4 + 0] + r.y * w1[q * 4 + 1]
                     + r.z * w1[q * 4 + 2] + r.w * w1[q * 4 + 3];
                ws2 += r.x * w2[q * 4 + 0] + r.y * w2[q * 4 + 1]
                     + r.z * w2[q * 4 + 2] + r.w * w2[q * 4 + 3];
            }
            ws0 *= env; ws1 *= env; ws2 *= env;
            const float* pj = &phi[(size_t)j * F3];
            const float* vj = &vin[(size_t)j * F3];
            float inv0 = pj[f]            * ws0;
            float inv1 = pj[FEAT + f]     * ws1;
            float inv2 = pj[2 * FEAT + f] * ws2;
            accs += inv1;
            av0 += inv0 * vj[f]            + inv2 * ux;
            av1 += inv0 * vj[FEAT + f]     + inv2 * uy;
            av2 += inv0 * vj[2 * FEAT + f] + inv2 * uz;
        }
        s[(size_t)a * FEAT + f] += accs;
        const float* va = &vin[(size_t)a * F3];
        float* vo = &vout[(size_t)a * F3];
        vo[f]            = va[f]            + av0;
        vo[FEAT + f]     = va[FEAT + f]     + av1;
        vo[2 * FEAT + f] = va[2 * FEAT + f] + av2;
    }
}

// ---------------- vv-norm + stack [s | ||v_v||] ----------------------------
__global__ void stack_kernel(int N)
{
    int idx = blockIdx.x * blockDim.x + threadIdx.x;
    if (idx >= N * FEAT) return;
    int n = idx >> 7, g = idx & 127;
    float a = g_vv[n * F3 + g];
    float b = g_vv[n * F3 + FEAT + g];
    float c = g_vv[n * F3 + 2 * FEAT + g];
    g_stack[n * 2 * FEAT + g] = g_s[idx];
    g_stack[n * 2 * FEAT + FEAT + g] = sqrtf(a * a + b * b + c * c + 1e-15f);
}

// ---------------- per-atom update ------------------------------------------
__global__ void update_kernel(float* __restrict__ v, int N)
{
    int idx = blockIdx.x * blockDim.x + threadIdx.x;
    if (idx >= N * FEAT) return;
    int n = idx >> 7, g = idx & 127;
    float sp0 = g_sp[n * F3 + g];
    float sp1 = g_sp[n * F3 + FEAT + g];
    float sp2 = g_sp[n * F3 + 2 * FEAT + g];
    float acc = 0.f;
#pragma unroll
    for (int d = 0; d < 3; d++) {
        float uv = g_uv[n * F3 + d * FEAT + g];
        v[n * F3 + d * FEAT + g] += uv * sp0;
        acc += uv * g_vv[n * F3 + d * FEAT + g];
    }
    g_s[idx] += acc * sp1 + sp2;
}

// ---------------- force readout: warp per edge, t = s@W1 precomputed -------
__global__ __launch_bounds__(256) void readout_kernel(
    const float* __restrict__ xyz,
    const int2* __restrict__ nbr,
    const float* __restrict__ b1,
    const float* __restrict__ w2,
    const float* __restrict__ b2v,
    float* __restrict__ out, int E)
{
    __shared__ float sb1[64], sw2[64];
    int tid = threadIdx.x;   // 256 = 8 warps
    if (tid < 64) { sb1[tid] = b1[tid]; sw2[tid] = w2[tid]; }
    __syncthreads();
    float b2 = b2v[0];
    int warp = tid >> 5, lane = tid & 31;
    int nwarps = gridDim.x * 8;
    for (int e = blockIdx.x * 8 + warp; e < E; e += nwarps) {
        int2 ij = nbr[e];
        const float* ti = &g_t[(size_t)ij.x * 64];
        const float* tj = &g_t[(size_t)ij.y * 64];
        float h0 = ti[lane]      + tj[lane]      + sb1[lane];
        float h1 = ti[lane + 32] + tj[lane + 32] + sb1[lane + 32];
        float p = silu_f(h0) * sw2[lane] + silu_f(h1) * sw2[lane + 32];
#pragma unroll
        for (int o = 16; o; o >>= 1) p += __shfl_xor_sync(0xffffffffu, p, o);
        float fs = p + b2;
        float dx = xyz[ij.x * 3 + 0] - xyz[ij.y * 3 + 0];
        float dy = xyz[ij.x * 3 + 1] - xyz[ij.y * 3 + 1];
        float dz = xyz[ij.x * 3 + 2] - xyz[ij.y * 3 + 2];
        float dis = sqrtf(dx * dx + dy * dy + dz * dz);
        if (lane < 3) {
            float dcomp = (lane == 0) ? dx : (lane == 1) ? dy : dz;
            float fe = fs * dcomp / dis;
            atomicAdd(&out[ij.x * 3 + lane], fe);
            atomicAdd(&out[ij.y * 3 + lane], -fe);
        }
    }
}

// ---------------- host orchestration ---------------------------------------
static void run_gemm(const float* A, const float* B, const float* bias, float* C,
                     int M, int N, int K, int act)
{
    dim3 grid(N / TBN, (M + TBM - 1) / TBM);
    gemm_kernel<<<grid, 256>>>(A, B, bias, C, M, N, K, act);
}

extern "C" void kernel_launch(void* const* d_in, const int* in_sizes, int n_in,
                              void* d_out, int out_size)
{
    const float* xyz    = (const float*)d_in[0];
    const int*   z      = (const int*)  d_in[1];
    const int2*  nbr    = (const int2*) d_in[2];
    const float* embed  = (const float*)d_in[3];
    const float* msg_w1 = (const float*)d_in[4];
    const float* msg_b1 = (const float*)d_in[5];
    const float* msg_w2 = (const float*)d_in[6];
    const float* msg_b2 = (const float*)d_in[7];
    const float* dist_w = (const float*)d_in[8];
    const float* dist_b = (const float*)d_in[9];
    const float* upd_u  = (const float*)d_in[10];
    const float* upd_v  = (const float*)d_in[11];
    const float* upd_w1 = (const float*)d_in[12];
    const float* upd_b1 = (const float*)d_in[13];
    const float* upd_w2 = (const float*)d_in[14];
    const float* upd_b2 = (const float*)d_in[15];
    const float* ero_w1 = (const float*)d_in[16];
    const float* ero_b1 = (const float*)d_in[17];
    const float* ero_w2 = (const float*)d_in[18];
    const float* ero_b2 = (const float*)d_in[19];

    const int N = in_sizes[1];          // 10000
    const int E = in_sizes[2] / 2;      // 160000

    float *s_p, *vA_p, *vB_p, *phi_p, *h_p, *stk_p, *uv_p, *vv_p, *sp_p, *t_p;
    int *deg_p, *cur_p;
    cudaGetSymbolAddress((void**)&s_p,   g_s);
    cudaGetSymbolAddress((void**)&vA_p,  g_vA);
    cudaGetSymbolAddress((void**)&vB_p,  g_vB);
    cudaGetSymbolAddress((void**)&phi_p, g_phi);
    cudaGetSymbolAddress((void**)&h_p,   g_h);
    cudaGetSymbolAddress((void**)&stk_p, g_stack);
    cudaGetSymbolAddress((void**)&uv_p,  g_uv);
    cudaGetSymbolAddress((void**)&vv_p,  g_vv);
    cudaGetSymbolAddress((void**)&sp_p,  g_sp);
    cudaGetSymbolAddress((void**)&t_p,   g_t);
    cudaGetSymbolAddress((void**)&deg_p, g_deg);
    cudaGetSymbolAddress((void**)&cur_p, g_cur);

    const size_t VBYTES = (size_t)N * F3 * sizeof(float);

    // init (phi for layer 0 computed early so a gemm lands in the ncu window)
    cudaMemsetAsync(vA_p, 0, VBYTES, 0);
    cudaMemsetAsync(d_out, 0, (size_t)out_size * sizeof(float), 0);
    init_s_kernel<<<(N * FEAT + 255) / 256, 256>>>(embed, z, N);
    edge_pre_kernel<<<(E + 255) / 256, 256>>>(xyz, nbr, E);
    run_gemm(s_p, msg_w1, msg_b1, h_p, N, FEAT, FEAT, 1);
    run_gemm(h_p, msg_w2, msg_b2, phi_p, N, F3, FEAT, 0);

    // CSR build
    cudaMemsetAsync(deg_p, 0, N * sizeof(int), 0);
    cudaMemsetAsync(cur_p, 0, N * sizeof(int), 0);
    hist_kernel<<<(E + 255) / 256, 256>>>(nbr, E);
    scan_kernel<<<1, 1024>>>(N);
    scatter_kernel<<<(E + 255) / 256, 256>>>(nbr, E);
    sortcsr_kernel<<<(N + 127) / 128, 128>>>(N);

    float* vcur = vA_p;
    float* vnxt = vB_p;
    for (int l = 0; l < 3; l++) {
        // gather message pass: s in place, v out-of-place (phi already ready)
        msg_csr_kernel<<<2048, 128>>>(nbr, phi_p, vcur, vnxt, s_p,
                                      dist_w + (size_t)l * NRBF * F3,
                                      dist_b + l * F3, N);
        // update stage: fused u/v GEMM (A loaded once per block)
        {
            dim3 grid(FEAT / TBN, (N * 3 + TBM - 1) / TBM);
            gemm_dual_kernel<<<grid, 256>>>(vnxt,
                                            upd_u + (size_t)l * FEAT * FEAT, uv_p,
                                            upd_v + (size_t)l * FEAT * FEAT, vv_p,
                                            N * 3);
        }
        stack_kernel<<<(N * FEAT + 255) / 256, 256>>>(N);
        run_gemm(stk_p, upd_w1 + (size_t)l * 2 * FEAT * FEAT, upd_b1 + l * FEAT,
                 h_p, N, FEAT, 2 * FEAT, 1);
        run_gemm(h_p, upd_w2 + (size_t)l * FEAT * F3, upd_b2 + l * F3,
                 sp_p, N, F3, FEAT, 0);
        update_kernel<<<(N * FEAT + 255) / 256, 256>>>(vnxt, N);
        // phi for next layer (depends on updated s)
        if (l < 2) {
            run_gemm(s_p, msg_w1 + (size_t)(l + 1) * FEAT * FEAT,
                     msg_b1 + (l + 1) * FEAT, h_p, N, FEAT, FEAT, 1);
            run_gemm(h_p, msg_w2 + (size_t)(l + 1) * FEAT * F3,
                     msg_b2 + (l + 1) * F3, phi_p, N, F3, FEAT, 0);
        }
        float* t = vcur; vcur = vnxt; vnxt = t;
    }

    // readout: t = s @ ero_w1 (no bias), then light edge kernel
    run_gemm(s_p, ero_w1, nullptr, t_p, N, 64, FEAT, 0);
    readout_kernel<<<2048, 256>>>(xyz, nbr, ero_b1, ero_w2, ero_b2,
                                  (float*)d_out, E);
}